// round 1
// baseline (speedup 1.0000x reference)
#include <cuda_runtime.h>

// FastECT: hist over (batch, bin, theta) then cumsum over bins.
// N=200000 points (D=3), T=128 thetas, R=128 bins, B=64 batches (batch sorted).
//
// Kernel 1 (k_hist): grid (S splits, B batches), 128 threads. Thread t owns
// theta t's smem histogram column exclusively -> race-free LDS/FADD/STS, no
// atomics. Points staged through smem tiles (broadcast reads). Flush each
// block's 128x128 partial hist to __device__ scratch with coalesced stores.
// Kernel 2 (k_merge): per batch, sum S partials + fused cumsum + write out.

#define TT 128      // num_thetas
#define RR 128      // resolution
#define BB 64       // batch_size
#define SS 4        // splits per batch -> 256 blocks
#define HSTRIDE 129 // smem column stride: flush read bank = (t+bin)%32, conflict-free
#define TILE 512    // points staged per smem tile

// scratch[b][s][bin][t]  (64 MB, static device allocation -- allowed)
__device__ float g_scratch[(size_t)BB * SS * RR * TT];

__device__ __forceinline__ int lower_bound_i32(const int* __restrict__ a, int n, int key) {
    int lo = 0, hi = n;
    while (lo < hi) {
        int mid = (lo + hi) >> 1;
        if (a[mid] < key) lo = mid + 1; else hi = mid;
    }
    return lo;
}

// bin = clip(floor((x.v + 1) * 64), 0, 127); match reference op order:
// separate add and mul (XLA keeps them as distinct HLOs), fma chain for the dot.
__device__ __forceinline__ int bin_of(float x0, float x1, float x2,
                                      float v0, float v1, float v2) {
    float nh = fmaf(x2, v2, fmaf(x1, v1, __fmul_rn(x0, v0)));
    float f  = __fmul_rn(__fadd_rn(nh, 1.0f), 64.0f);
    int bin  = __float2int_rd(f);          // floor, saturating
    bin = max(0, min(RR - 1, bin));
    return bin;
}

extern __shared__ float smem_dyn[];

__global__ void __launch_bounds__(128)
k_hist(const float* __restrict__ x, const float* __restrict__ v,
       const int* __restrict__ batch, int n) {
    float* sh = smem_dyn;                  // [TT * HSTRIDE] histogram
    float* xs = smem_dyn + TT * HSTRIDE;   // [TILE * 3] staged points
    __shared__ int range[2];

    const int t = threadIdx.x;             // theta owned by this thread
    const int b = blockIdx.y;              // batch
    const int s = blockIdx.x;              // split

    if (t == 0) {
        int s0  = lower_bound_i32(batch, n, b);
        int e0  = lower_bound_i32(batch, n, b + 1);
        int cnt = e0 - s0;
        range[0] = s0 + (cnt * s) / SS;
        range[1] = s0 + (cnt * (s + 1)) / SS;
    }
    // zero this block's histogram
    for (int i = t; i < TT * HSTRIDE; i += 128) sh[i] = 0.0f;

    const float v0 = v[t];
    const float v1 = v[TT + t];
    const float v2 = v[2 * TT + t];
    __syncthreads();

    const int lo = range[0], hi = range[1];
    float* col = sh + t * HSTRIDE;

    for (int base = lo; base < hi; base += TILE) {
        const int m = min(TILE, hi - base);
        // stage m points (3 floats each), coalesced
        for (int i = t; i < m * 3; i += 128) xs[i] = x[(size_t)base * 3 + i];
        __syncthreads();

        int k = 0;
        for (; k + 4 <= m; k += 4) {
            float a0 = xs[3*k+0],  a1 = xs[3*k+1],  a2 = xs[3*k+2];
            float b0 = xs[3*k+3],  b1 = xs[3*k+4],  b2 = xs[3*k+5];
            float c0 = xs[3*k+6],  c1 = xs[3*k+7],  c2 = xs[3*k+8];
            float d0 = xs[3*k+9],  d1 = xs[3*k+10], d2 = xs[3*k+11];
            int ba = bin_of(a0, a1, a2, v0, v1, v2);
            int bb = bin_of(b0, b1, b2, v0, v1, v2);
            int bc = bin_of(c0, c1, c2, v0, v1, v2);
            int bd = bin_of(d0, d1, d2, v0, v1, v2);
            col[ba] += 1.0f;   // thread-exclusive column: plain RMW is safe
            col[bb] += 1.0f;
            col[bc] += 1.0f;
            col[bd] += 1.0f;
        }
        for (; k < m; ++k) {
            int bn = bin_of(xs[3*k], xs[3*k+1], xs[3*k+2], v0, v1, v2);
            col[bn] += 1.0f;
        }
        __syncthreads();
    }

    // flush partial hist -> scratch[b][s][bin][t]; smem read is conflict-free
    // ((t*129+bin)%32 = (t+bin)%32 distinct across lanes), stores coalesced.
    float* dst = g_scratch + (size_t)(b * SS + s) * RR * TT;
    for (int bin = 0; bin < RR; ++bin)
        dst[bin * TT + t] = sh[t * HSTRIDE + bin];
}

__global__ void __launch_bounds__(128)
k_merge(float* __restrict__ out) {
    const int t = threadIdx.x;
    const int b = blockIdx.x;
    const float* src = g_scratch + (size_t)b * SS * RR * TT;

    float acc = 0.0f;
#pragma unroll 8
    for (int bin = 0; bin < RR; ++bin) {
        float h0 = src[(0 * RR + bin) * TT + t];
        float h1 = src[(1 * RR + bin) * TT + t];
        float h2 = src[(2 * RR + bin) * TT + t];
        float h3 = src[(3 * RR + bin) * TT + t];
        acc += (h0 + h1) + (h2 + h3);
        out[((size_t)b * RR + bin) * TT + t] = acc;
    }
}

extern "C" void kernel_launch(void* const* d_in, const int* in_sizes, int n_in,
                              void* d_out, int out_size) {
    const float* x     = (const float*)d_in[0];   // [200000, 3]
    const float* v     = (const float*)d_in[1];   // [3, 128]
    const int*   batch = (const int*)d_in[2];     // [200000], sorted
    const int n = in_sizes[2];

    const int smem_bytes = (TT * HSTRIDE + TILE * 3) * (int)sizeof(float); // 72192
    cudaFuncSetAttribute(k_hist, cudaFuncAttributeMaxDynamicSharedMemorySize, smem_bytes);

    k_hist<<<dim3(SS, BB), 128, smem_bytes>>>(x, v, batch, n);
    k_merge<<<BB, 128>>>((float*)d_out);
}

// round 2
// speedup vs baseline: 1.4045x; 1.4045x over previous
#include <cuda_runtime.h>

// FastECT: per-(batch,bin,theta) histogram + cumsum over bins.
// N=200000 pts (D=3), T=128 thetas, R=128 bins, B=64 batches, batch sorted.
//
// k_zero: zero d_out (poisoned 0xAA).
// k_hist: 444 blocks (=148 SMs x 3 resident) x 128 threads over flat equal
//   point ranges. Thread t exclusively owns theta t's 128-bin smem column
//   (stride 129 words -> bank (t+bin)%32) => race-free LDS/FADD/STS, no
//   atomics in the hot loop. Points staged as float4 (1 broadcast wavefront).
//   Since cumsum is linear, each block flushes cumsum(partial hist) directly
//   into d_out with atomicAdd (REDG) -- no merge kernel, no global scratch.
//   Blocks spanning a (sorted) batch boundary flush per contiguous segment.

#define TT 128
#define RR 128
#define BB 64
#define NBLK 444     // 148 SMs * 3 resident blocks -> balanced single wave
#define HSTRIDE 129  // hist column stride (words): conflict-free patterns
#define TILE 256     // points staged per tile (float4 each)

__device__ __forceinline__ int lower_bound_i32(const int* __restrict__ a, int n, int key) {
    int lo = 0, hi = n;
    while (lo < hi) {
        int mid = (lo + hi) >> 1;
        if (a[mid] < key) lo = mid + 1; else hi = mid;
    }
    return lo;
}

// bin = clip(floor((x.v + 1) * 64), 0, 127); op order matches reference HLOs.
__device__ __forceinline__ int bin_of(float x0, float x1, float x2,
                                      float v0, float v1, float v2) {
    float nh = fmaf(x2, v2, fmaf(x1, v1, __fmul_rn(x0, v0)));
    float f  = __fmul_rn(__fadd_rn(nh, 1.0f), 64.0f);
    int bin  = __float2int_rd(f);
    return max(0, min(RR - 1, bin));
}

extern __shared__ float smem_dyn[];

__global__ void __launch_bounds__(256)
k_zero(float* __restrict__ out, int n4) {
    int i = blockIdx.x * blockDim.x + threadIdx.x;
    if (i < n4) ((float4*)out)[i] = make_float4(0.f, 0.f, 0.f, 0.f);
}

__global__ void __launch_bounds__(128)
k_hist(const float* __restrict__ x, const float* __restrict__ v,
       const int* __restrict__ batch, int n, float* __restrict__ out) {
    float*  sh  = smem_dyn;                        // [TT * HSTRIDE] histogram
    float4* xs4 = (float4*)(smem_dyn + TT * HSTRIDE); // [TILE] staged points
    __shared__ int seg_end_sh;

    const int t = threadIdx.x;
    const int g = blockIdx.x;

    // flat equal-size point range for this block
    const int lo = (int)(((long long)g)     * n / NBLK);
    const int hi = (int)(((long long)g + 1) * n / NBLK);

    const float v0 = v[t];
    const float v1 = v[TT + t];
    const float v2 = v[2 * TT + t];

    float* col = sh + t * HSTRIDE;
    // zero own column only (bank (t+bin)%32, conflict-free; no sync needed)
#pragma unroll
    for (int i = 0; i < RR; ++i) col[i] = 0.0f;

    int pos = lo;
    while (pos < hi) {
        // current segment = run of one batch value (batch is sorted)
        if (t == 0) {
            int b = batch[pos];
            seg_end_sh = min(hi, lower_bound_i32(batch, n, b + 1));
        }
        __syncthreads();
        const int seg_end = seg_end_sh;
        const int b = batch[pos];   // L2 broadcast, all threads same value

        for (int base = pos; base < seg_end; base += TILE) {
            const int m = min(TILE, seg_end - base);
            // stage m points as float4 (w unused)
            for (int p = t; p < m; p += 128) {
                const float* src = x + (size_t)(base + p) * 3;
                xs4[p] = make_float4(src[0], src[1], src[2], 0.0f);
            }
            __syncthreads();

            int k = 0;
            for (; k + 4 <= m; k += 4) {
                float4 a = xs4[k], bq = xs4[k+1], c = xs4[k+2], d = xs4[k+3];
                int ba = bin_of(a.x,  a.y,  a.z,  v0, v1, v2);
                int bb = bin_of(bq.x, bq.y, bq.z, v0, v1, v2);
                int bc = bin_of(c.x,  c.y,  c.z,  v0, v1, v2);
                int bd = bin_of(d.x,  d.y,  d.z,  v0, v1, v2);
                col[ba] += 1.0f;   // thread-exclusive column: plain RMW safe
                col[bb] += 1.0f;
                col[bc] += 1.0f;
                col[bd] += 1.0f;
            }
            for (; k < m; ++k) {
                float4 a = xs4[k];
                col[bin_of(a.x, a.y, a.z, v0, v1, v2)] += 1.0f;
            }
            __syncthreads();
        }

        // flush: cumsum of own column, atomic-add into out[b][bin][t].
        // cumsum is linear => sum over blocks of cumsum(partial) == ECT.
        // smem reads conflict-free (same bin across lanes -> distinct banks),
        // REDG coalesced across t. Integer float adds -> exact/deterministic.
        {
            float acc = 0.0f;
            float* dst = out + ((size_t)b * RR) * TT + t;
#pragma unroll 8
            for (int bin = 0; bin < RR; ++bin) {
                acc += col[bin];
                atomicAdd(dst + (size_t)bin * TT, acc);
                col[bin] = 0.0f;   // rezero own column for next segment
            }
        }
        pos = seg_end;
        __syncthreads();   // protect xs4 reuse across segments
    }
}

extern "C" void kernel_launch(void* const* d_in, const int* in_sizes, int n_in,
                              void* d_out, int out_size) {
    const float* x     = (const float*)d_in[0];   // [200000, 3]
    const float* v     = (const float*)d_in[1];   // [3, 128]
    const int*   batch = (const int*)d_in[2];     // [200000], sorted
    const int n = in_sizes[2];

    float* out = (float*)d_out;                   // [64, 128, 128]
    const int n4 = out_size / 4;                  // 262144 float4

    const int smem_bytes = (TT * HSTRIDE) * 4 + TILE * 16;  // 66048+4096=70144
    cudaFuncSetAttribute(k_hist, cudaFuncAttributeMaxDynamicSharedMemorySize, smem_bytes);

    k_zero<<<(n4 + 255) / 256, 256>>>(out, n4);
    k_hist<<<NBLK, 128, smem_bytes>>>(x, v, batch, n, out);
}

// round 3
// speedup vs baseline: 1.4544x; 1.0355x over previous
#include <cuda_runtime.h>

// FastECT: per-(batch,bin,theta) histogram + cumsum over bins.
// N=200000 pts (D=3), T=128 thetas, R=128 bins, B=64 batches, batch sorted.
//
// k_zero: zero d_out (poisoned 0xAA).
// k_hist: 888 blocks (=148 SMs x 6 resident) x 128 threads over flat equal
//   point ranges. Histogram is BIN-MAJOR u16 in smem: h[bin*128 + t].
//   Bank = t%32 -> every RMW / flush / zero is exactly conflict-free,
//   independent of the (data-dependent) bin. Thread t exclusively owns
//   theta t => race-free plain LDS/IADD/STS, no atomics in the hot loop.
//   u16 counts (<= ~500 per block-bin) halve smem -> 6 blocks/SM (24 warps).
//   cumsum is linear, so each block flushes cumsum(partial) straight into
//   d_out with f32 atomicAdd (exact integer adds, deterministic).

#define TT 128
#define RR 128
#define NBLK 888     // 148 SMs * 6 resident blocks, single balanced wave
#define TILE 256     // points staged per tile (float4 each)

__device__ __forceinline__ int lower_bound_i32(const int* __restrict__ a, int n, int key) {
    int lo = 0, hi = n;
    while (lo < hi) {
        int mid = (lo + hi) >> 1;
        if (a[mid] < key) lo = mid + 1; else hi = mid;
    }
    return lo;
}

// bin = clip(floor((x.v + 1) * 64), 0, 127); op order matches reference HLOs.
__device__ __forceinline__ int bin_of(float x0, float x1, float x2,
                                      float v0, float v1, float v2) {
    float nh = fmaf(x2, v2, fmaf(x1, v1, __fmul_rn(x0, v0)));
    float f  = __fmul_rn(__fadd_rn(nh, 1.0f), 64.0f);
    int bin  = __float2int_rd(f);
    return max(0, min(RR - 1, bin));
}

extern __shared__ unsigned short smem_dyn[];

__global__ void __launch_bounds__(256)
k_zero(float* __restrict__ out, int n4) {
    int i = blockIdx.x * blockDim.x + threadIdx.x;
    if (i < n4) ((float4*)out)[i] = make_float4(0.f, 0.f, 0.f, 0.f);
}

__global__ void __launch_bounds__(128)
k_hist(const float* __restrict__ x, const float* __restrict__ v,
       const int* __restrict__ batch, int n, float* __restrict__ out) {
    unsigned short* h = smem_dyn;                       // [RR*TT] bin-major u16
    float4* xs4 = (float4*)(smem_dyn + RR * TT);        // [TILE] staged points
    __shared__ int seg_end_sh;

    const int t = threadIdx.x;
    const int g = blockIdx.x;

    const int lo = (int)(((long long)g)     * n / NBLK);
    const int hi = (int)(((long long)g + 1) * n / NBLK);

    const float v0 = v[t];
    const float v1 = v[TT + t];
    const float v2 = v[2 * TT + t];

    // zero histogram: 16384B as 1024 uint4 stores, conflict-free
    {
        uint4* hz = (uint4*)h;
        for (int i = t; i < (RR * TT) / 8; i += 128)
            hz[i] = make_uint4(0u, 0u, 0u, 0u);
    }

    int pos = lo;
    while (pos < hi) {
        if (t == 0) {
            int b = batch[pos];
            seg_end_sh = min(hi, lower_bound_i32(batch, n, b + 1));
        }
        __syncthreads();
        const int seg_end = seg_end_sh;
        const int b = batch[pos];            // uniform (L2/const broadcast)

        for (int base = pos; base < seg_end; base += TILE) {
            const int m = min(TILE, seg_end - base);
            for (int p = t; p < m; p += 128) {
                const float* src = x + (size_t)(base + p) * 3;
                xs4[p] = make_float4(src[0], src[1], src[2], 0.0f);
            }
            __syncthreads();

            unsigned short* ht = h + t;      // lane-fixed base -> bank t%32
            int k = 0;
            for (; k + 4 <= m; k += 4) {
                float4 a = xs4[k], bq = xs4[k+1], c = xs4[k+2], d = xs4[k+3];
                int ba = bin_of(a.x,  a.y,  a.z,  v0, v1, v2);
                int bb = bin_of(bq.x, bq.y, bq.z, v0, v1, v2);
                int bc = bin_of(c.x,  c.y,  c.z,  v0, v1, v2);
                int bd = bin_of(d.x,  d.y,  d.z,  v0, v1, v2);
                ht[ba << 7] = (unsigned short)(ht[ba << 7] + 1);  // exclusive
                ht[bb << 7] = (unsigned short)(ht[bb << 7] + 1);
                ht[bc << 7] = (unsigned short)(ht[bc << 7] + 1);
                ht[bd << 7] = (unsigned short)(ht[bd << 7] + 1);
            }
            for (; k < m; ++k) {
                float4 a = xs4[k];
                int bn = bin_of(a.x, a.y, a.z, v0, v1, v2);
                ht[bn << 7] = (unsigned short)(ht[bn << 7] + 1);
            }
            __syncthreads();
        }

        // flush: cumsum(own partial) += into out[b][bin][t] (linear in hist).
        // LDS conflict-free (bank t%32), REDG coalesced across t.
        {
            float acc = 0.0f;
            unsigned short* ht = h + t;
            float* dst = out + ((size_t)b * RR) * TT + t;
#pragma unroll 8
            for (int bin = 0; bin < RR; ++bin) {
                acc += (float)ht[bin << 7];
                atomicAdd(dst + (size_t)bin * TT, acc);
                ht[bin << 7] = 0;            // rezero for next segment
            }
        }
        pos = seg_end;
        __syncthreads();                     // protect xs4 / h reuse
    }
}

extern "C" void kernel_launch(void* const* d_in, const int* in_sizes, int n_in,
                              void* d_out, int out_size) {
    const float* x     = (const float*)d_in[0];   // [200000, 3]
    const float* v     = (const float*)d_in[1];   // [3, 128]
    const int*   batch = (const int*)d_in[2];     // [200000], sorted
    const int n = in_sizes[2];

    float* out = (float*)d_out;                   // [64, 128, 128]
    const int n4 = out_size / 4;

    const int smem_bytes = RR * TT * 2 + TILE * 16;   // 32768 + 4096 = 36864
    cudaFuncSetAttribute(k_hist, cudaFuncAttributeMaxDynamicSharedMemorySize, smem_bytes);

    k_zero<<<(n4 + 255) / 256, 256>>>(out, n4);
    k_hist<<<NBLK, 128, smem_bytes>>>(x, v, batch, n, out);
}

// round 5
// speedup vs baseline: 1.5323x; 1.0536x over previous
#include <cuda_runtime.h>

// FastECT: per-(batch,bin,theta) histogram + cumsum over bins.
// N=200000 pts (D=3), T=128 thetas, R=128 bins, B=64 batches, batch sorted.
//
// k_zero: zero d_out (poisoned 0xAA).
// k_hist: 1184 blocks (=148 SMs x 8 resident) x 128 threads over flat equal
//   point ranges. Histogram: u8 counts, 4 bins packed per 32-bit word per
//   thread: byte addr = ((bin&~3)<<7) + (t<<2) + (bin&3). Word index =
//   (bin>>2)*128 + t -> bank = t%32 for ANY bin => every RMW / flush / zero
//   is exactly conflict-free. Thread t owns theta t => race-free, no atomics
//   in the hot loop. u8 exact: per-segment counts <= points/block = 169 < 256.
//   cumsum is linear => each block flushes cumsum(partial) into d_out with
//   f32 atomicAdd (exact integer adds, deterministic).

#define TT 128
#define RR 128
#define NBLK 1184    // 148 SMs * 8 resident blocks, single balanced wave
#define TILE 256     // points staged per tile (float4 each)

typedef unsigned int  u32;
typedef unsigned char u8;

__device__ __forceinline__ int lower_bound_i32(const int* __restrict__ a, int n, int key) {
    int lo = 0, hi = n;
    while (lo < hi) {
        int mid = (lo + hi) >> 1;
        if (a[mid] < key) lo = mid + 1; else hi = mid;
    }
    return lo;
}

// bin = clip(floor((x.v + 1) * 64), 0, 127); op order matches reference HLOs.
__device__ __forceinline__ int bin_of(float x0, float x1, float x2,
                                      float v0, float v1, float v2) {
    float nh = fmaf(x2, v2, fmaf(x1, v1, __fmul_rn(x0, v0)));
    float f  = __fmul_rn(__fadd_rn(nh, 1.0f), 64.0f);
    int bin  = __float2int_rd(f);
    return max(0, min(RR - 1, bin));
}

// conflict-free u8 slot for (thread t, bin): word = (bin>>2)*128 + t -> bank t%32
__device__ __forceinline__ int haddr(int t4, int bin) {
    return ((bin & ~3) << 7) + t4 + (bin & 3);   // t4 = t<<2 (bytes)
}

extern __shared__ u8 smem_dyn[];

__global__ void __launch_bounds__(256)
k_zero(float* __restrict__ out, int n4) {
    int i = blockIdx.x * blockDim.x + threadIdx.x;
    if (i < n4) ((float4*)out)[i] = make_float4(0.f, 0.f, 0.f, 0.f);
}

__global__ void __launch_bounds__(128, 8)
k_hist(const float* __restrict__ x, const float* __restrict__ v,
       const int* __restrict__ batch, int n, float* __restrict__ out) {
    u8* h = smem_dyn;                                // [RR*TT] u8, packed
    float4* xs4 = (float4*)(smem_dyn + RR * TT);     // [TILE] staged points
    __shared__ int seg_end_sh;

    const int t  = threadIdx.x;
    const int t4 = t << 2;
    const int g  = blockIdx.x;

    const int lo = (int)(((long long)g)     * n / NBLK);
    const int hi = (int)(((long long)g + 1) * n / NBLK);

    const float v0 = v[t];
    const float v1 = v[TT + t];
    const float v2 = v[2 * TT + t];

    // zero 16KB histogram as uint4 (conflict-free)
    {
        uint4* hz = (uint4*)h;
        for (int i = t; i < (RR * TT) / 16; i += 128)
            hz[i] = make_uint4(0u, 0u, 0u, 0u);
    }

    int pos = lo;
    while (pos < hi) {
        if (t == 0) {
            int b = batch[pos];
            seg_end_sh = min(hi, lower_bound_i32(batch, n, b + 1));
        }
        __syncthreads();
        const int seg_end = seg_end_sh;
        const int b = batch[pos];                    // uniform broadcast

        for (int base = pos; base < seg_end; base += TILE) {
            const int m = min(TILE, seg_end - base);
            for (int p = t; p < m; p += 128) {
                const float* src = x + (size_t)(base + p) * 3;
                xs4[p] = make_float4(src[0], src[1], src[2], 0.0f);
            }
            __syncthreads();

            int k = 0;
            for (; k + 8 <= m; k += 8) {
                int bn[8];
#pragma unroll
                for (int j = 0; j < 8; ++j) {
                    float4 p = xs4[k + j];
                    bn[j] = bin_of(p.x, p.y, p.z, v0, v1, v2);
                }
#pragma unroll
                for (int j = 0; j < 8; ++j) {
                    int a = haddr(t4, bn[j]);
                    h[a] = (u8)(h[a] + 1);           // exclusive slot
                }
            }
            for (; k < m; ++k) {
                float4 p = xs4[k];
                int a = haddr(t4, bin_of(p.x, p.y, p.z, v0, v1, v2));
                h[a] = (u8)(h[a] + 1);
            }
            __syncthreads();
        }

        // flush: cumsum(own partial) += into out[b][bin][t].
        // One LDS.32 per 4 bins (word (bin>>2)*128 + t, bank t%32), REDG coalesced.
        {
            int acc = 0;
            u32* hw = (u32*)h;
            float* dst = out + ((size_t)b * RR) * TT + t;
#pragma unroll 4
            for (int bin4 = 0; bin4 < RR / 4; ++bin4) {
                u32 w = hw[bin4 * 128 + t];
                hw[bin4 * 128 + t] = 0u;             // rezero for next segment
                acc += (int)(w & 255u);
                atomicAdd(dst + (size_t)(bin4 * 4 + 0) * TT, (float)acc);
                acc += (int)((w >> 8) & 255u);
                atomicAdd(dst + (size_t)(bin4 * 4 + 1) * TT, (float)acc);
                acc += (int)((w >> 16) & 255u);
                atomicAdd(dst + (size_t)(bin4 * 4 + 2) * TT, (float)acc);
                acc += (int)(w >> 24);
                atomicAdd(dst + (size_t)(bin4 * 4 + 3) * TT, (float)acc);
            }
        }
        pos = seg_end;
        __syncthreads();                             // protect xs4 / h reuse
    }
}

extern "C" void kernel_launch(void* const* d_in, const int* in_sizes, int n_in,
                              void* d_out, int out_size) {
    const float* x     = (const float*)d_in[0];   // [200000, 3]
    const float* v     = (const float*)d_in[1];   // [3, 128]
    const int*   batch = (const int*)d_in[2];     // [200000], sorted
    const int n = in_sizes[2];

    float* out = (float*)d_out;                   // [64, 128, 128]
    const int n4 = out_size / 4;

    const int smem_bytes = RR * TT + TILE * 16;   // 16384 + 4096 = 20480
    cudaFuncSetAttribute(k_hist, cudaFuncAttributeMaxDynamicSharedMemorySize, smem_bytes);

    k_zero<<<(n4 + 255) / 256, 256>>>(out, n4);
    k_hist<<<NBLK, 128, smem_bytes>>>(x, v, batch, n, out);
}